// round 17
// baseline (speedup 1.0000x reference)
#include <cuda_runtime.h>
#include <cuda_bf16.h>
#include <stdint.h>

#define D_DIM 256
#define NROWS 8192
#define KCODES 8192
#define NTILES 64        // KCODES / 128 column tiles
#define NJOBS 4096       // phase1 tile count
#define NROWJOBS 1024    // phase2 row-groups (8 rows each)
#define CAP 96
#define MARGIN 2e-4f

// ---------------- device scratch (no allocations allowed) ----------------
__device__ float g_x2[NROWS];
__device__ float g_c2[KCODES];
__device__ unsigned long long g_part[NROWS * NTILES];
__device__ double g_loss_part[NROWJOBS];
__device__ __nv_bfloat16 g_ab[NROWS * D_DIM];   // z_e rounded to bf16
__device__ __nv_bfloat16 g_bb[KCODES * D_DIM];  // codebook rounded to bf16
__device__ int g_ccnt[NROWS];
__device__ unsigned long long g_cand[NROWS * CAP];
__device__ unsigned int g_bar;                  // grid barrier counter

// ------------------------------ helpers ----------------------------------
__device__ __forceinline__ uint32_t smem_u32(const void* p) {
    uint32_t a;
    asm("{ .reg .u64 t; cvta.to.shared.u64 t, %1; cvt.u32.u64 %0, t; }"
        : "=r"(a) : "l"(p));
    return a;
}
__device__ __forceinline__ void cpa16(uint32_t d, const void* s) {
    asm volatile("cp.async.cg.shared.global [%0], [%1], 16;"
                 :: "r"(d), "l"(s) : "memory");
}
__device__ __forceinline__ void ldsm4(uint32_t* r, uint32_t a) {
    asm volatile("ldmatrix.sync.aligned.m8n8.x4.shared.b16 {%0,%1,%2,%3}, [%4];"
                 : "=r"(r[0]), "=r"(r[1]), "=r"(r[2]), "=r"(r[3]) : "r"(a));
}
__device__ __forceinline__ void mma16816(float* d, const uint32_t* a,
                                         const uint32_t* b) {
    asm volatile(
        "mma.sync.aligned.m16n8k16.row.col.f32.bf16.bf16.f32 "
        "{%0,%1,%2,%3}, {%4,%5,%6,%7}, {%8,%9}, {%0,%1,%2,%3};"
        : "+f"(d[0]), "+f"(d[1]), "+f"(d[2]), "+f"(d[3])
        : "r"(a[0]), "r"(a[1]), "r"(a[2]), "r"(a[3]), "r"(b[0]), "r"(b[1]));
}
#define SW(o) ((uint32_t)(o) ^ (((uint32_t)(o) >> 3) & 0x70u))

// device-wide barrier: all gridDim.x blocks arrive; monotonic target
__device__ __forceinline__ void grid_barrier(unsigned int target) {
    __syncthreads();
    if (threadIdx.x == 0) {
        __threadfence();
        atomicAdd(&g_bar, 1u);
        while (*(volatile unsigned int*)&g_bar < target) {}
        __threadfence();
    }
    __syncthreads();
}

// ------------- kernel 1: norms (exact R2 order) + bf16 copies ------------
__global__ void split_kernel(const float* __restrict__ ze,
                             const float* __restrict__ cb, int N, int K) {
    int gtid = blockIdx.x * blockDim.x + threadIdx.x;
    if (gtid < NROWS) g_ccnt[gtid] = 0;  // reset candidate counters each call
    if (gtid == 0) g_bar = 0;            // reset grid barrier each call
    int warp = gtid >> 5;
    int lane = threadIdx.x & 31;
    if (warp >= N + K) return;
    const float* src;
    float* dst;
    int row;
    bool is_code = (warp < K);
    if (is_code) { src = cb; dst = g_c2; row = warp; }
    else         { src = ze; dst = g_x2; row = warp - K; }
    const float* p = src + (size_t)row * D_DIM;
    float acc = 0.0f;
#pragma unroll
    for (int i = 0; i < D_DIM / 32; ++i) {
        float v = p[lane + 32 * i];
        acc = __fadd_rn(acc, __fmul_rn(v, v));
        __nv_bfloat16 h = __float2bfloat16(v);
        size_t off = (size_t)row * D_DIM + lane + 32 * i;
        if (is_code) g_bb[off] = h; else g_ab[off] = h;
    }
#pragma unroll
    for (int off = 16; off; off >>= 1)
        acc = __fadd_rn(acc, __shfl_down_sync(0xffffffffu, acc, off));
    if (lane == 0) dst[row] = acc;
}

// ---- fused persistent kernel: phase1 tiles + barrier + phase2 + loss ----
// grid = 2 * SM count (all blocks co-resident: 96KB dyn + ~1KB static/CTA).
__global__ __launch_bounds__(256, 2) void fused_kernel(
    const float* __restrict__ ze, const float* __restrict__ cb,
    float* __restrict__ out_zq, float* __restrict__ out_idx,
    float* __restrict__ out_loss) {
    cudaGridDependencySynchronize();  // PDL: wait for split_kernel grid
    extern __shared__ char dsm[];     // 96KB: 3 stages x (A 16KB + B 16KB)
    __shared__ float s_c2[128];
    __shared__ float s_x2[128];

    const int tid = threadIdx.x;
    const int wid = tid >> 5, lane = tid & 31;
    const int mw = wid >> 2, nw = wid & 3;
    const uint32_t sb = smem_u32(dsm);
    const unsigned int nblk = gridDim.x;

    // overlays into dead stage-1 region (valid only during epilogue)
    typedef unsigned long long ull;
    ull (*red)[64][4] = reinterpret_cast<ull(*)[64][4]>(dsm + 32768);
    ull* s_minkey = reinterpret_cast<ull*>(dsm + 36864);
    float* s_min = reinterpret_cast<float*>(dsm + 37888);

    // =================== phase 1: grid-stride over 4096 tiles ===========
    for (int t = blockIdx.x; t < NJOBS; t += nblk) {
        const int row0 = (t & 63) * 128;       // old blockIdx.x
        const int col0 = (t >> 6) * 128;       // old blockIdx.y

        if (tid < 128) {
            s_c2[tid] = g_c2[col0 + tid];
            s_x2[tid] = g_x2[row0 + tid];
        }

        float acc[4][4][4];
#pragma unroll
        for (int i = 0; i < 4; ++i)
#pragma unroll
            for (int j = 0; j < 4; ++j)
#pragma unroll
                for (int c = 0; c < 4; ++c) acc[i][j][c] = 0.0f;

        auto issue = [&](int ch) {
            uint32_t ab = sb + (uint32_t)(ch % 3) * 32768u;
            uint32_t bb = ab + 16384u;
            const __nv_bfloat16* ga = g_ab + (size_t)row0 * D_DIM + ch * 64;
            const __nv_bfloat16* gb = g_bb + (size_t)col0 * D_DIM + ch * 64;
#pragma unroll
            for (int q = 0; q < 4; ++q) {
                int lin = tid + q * 256;      // 0..1023
                int r = lin >> 3, gi = lin & 7;
                uint32_t off = SW(r * 128 + gi * 16);
                cpa16(ab + off, ga + (size_t)r * D_DIM + gi * 8);
                cpa16(bb + off, gb + (size_t)r * D_DIM + gi * 8);
            }
            asm volatile("cp.async.commit_group;" ::: "memory");
        };

        issue(0);
        issue(1);
        issue(2);
#pragma unroll
        for (int ch = 0; ch < 4; ++ch) {
            // group ch complete before use: 2,1,1,0 (provably safe)
            if (ch == 0)      asm volatile("cp.async.wait_group 2;" ::: "memory");
            else if (ch < 3)  asm volatile("cp.async.wait_group 1;" ::: "memory");
            else              asm volatile("cp.async.wait_group 0;" ::: "memory");
            __syncthreads();
            if (ch == 1) issue(3);
            uint32_t ab = sb + (uint32_t)(ch % 3) * 32768u;
            uint32_t bb = ab + 16384u;
#pragma unroll
            for (int ks = 0; ks < 4; ++ks) {
                uint32_t afr[4][4], bfr[4][2];
#pragma unroll
                for (int i = 0; i < 4; ++i) {
                    int r = mw * 64 + i * 16 + (lane & 15);
                    uint32_t off = SW(r * 128 + (ks * 16 + (lane >> 4) * 8) * 2);
                    ldsm4(afr[i], ab + off);
                }
#pragma unroll
                for (int j2 = 0; j2 < 2; ++j2) {
                    // non-trans: smem B is [n][k]; frag (n=l>>2, k=2(l%4))
                    int n = nw * 32 + j2 * 16 + (lane & 7) + ((lane >> 4) & 1) * 8;
                    uint32_t off = SW(n * 128 + (ks * 16 + ((lane >> 3) & 1) * 8) * 2);
                    uint32_t t4[4];
                    ldsm4(t4, bb + off);
                    bfr[j2 * 2 + 0][0] = t4[0]; bfr[j2 * 2 + 0][1] = t4[1];
                    bfr[j2 * 2 + 1][0] = t4[2]; bfr[j2 * 2 + 1][1] = t4[3];
                }
#pragma unroll
                for (int i = 0; i < 4; ++i)
#pragma unroll
                    for (int j = 0; j < 4; ++j) mma16816(acc[i][j], afr[i], bfr[j]);
            }
        }

        // ---- epilogue pass 1: float-domain argmin (first-min preserved) ----
        unsigned long long klo[4], khi[4];
#pragma unroll
        for (int i = 0; i < 4; ++i) {
            int rlo = mw * 64 + i * 16 + (lane >> 2);
            float x2lo = s_x2[rlo], x2hi = s_x2[rlo + 8];
            float dlo = 3.4e38f, dhi = 3.4e38f;
            int ilo = 0, ihi = 0;
#pragma unroll
            for (int j = 0; j < 4; ++j) {
                int c0 = nw * 32 + j * 8 + (lane & 3) * 2;
#pragma unroll
                for (int c = 0; c < 2; ++c) {
                    float d = __fadd_rn(
                        __fsub_rn(x2lo, __fmul_rn(2.0f, acc[i][j][c])), s_c2[c0 + c]);
                    if (d < dlo) { dlo = d; ilo = col0 + c0 + c; }
                    d = __fadd_rn(
                        __fsub_rn(x2hi, __fmul_rn(2.0f, acc[i][j][2 + c])), s_c2[c0 + c]);
                    if (d < dhi) { dhi = d; ihi = col0 + c0 + c; }
                }
            }
            klo[i] = ((unsigned long long)__float_as_uint(dlo) << 32) | (unsigned)ilo;
            khi[i] = ((unsigned long long)__float_as_uint(dhi) << 32) | (unsigned)ihi;
        }
#pragma unroll
        for (int s = 1; s <= 2; s <<= 1)
#pragma unroll
            for (int i = 0; i < 4; ++i) {
                unsigned long long o = __shfl_xor_sync(0xffffffffu, klo[i], s);
                if (o < klo[i]) klo[i] = o;
                o = __shfl_xor_sync(0xffffffffu, khi[i], s);
                if (o < khi[i]) khi[i] = o;
            }
        if ((lane & 3) == 0)
#pragma unroll
            for (int i = 0; i < 4; ++i) {
                red[mw][i * 16 + (lane >> 2)][nw] = klo[i];
                red[mw][i * 16 + (lane >> 2) + 8][nw] = khi[i];
            }
        __syncthreads();
        if (tid < 128) {
            unsigned long long m = red[tid >> 6][tid & 63][0];
#pragma unroll
            for (int q = 1; q < 4; ++q) {
                unsigned long long k = red[tid >> 6][tid & 63][q];
                if (k < m) m = k;
            }
            g_part[(size_t)(row0 + tid) * NTILES + (t >> 6)] = m;
            s_minkey[tid] = m;
            s_min[tid] = __uint_as_float((uint32_t)(m >> 32));
        }
        __syncthreads();
        // margin sweep: runner-ups within MARGIN of the tile min
#pragma unroll
        for (int i = 0; i < 4; ++i) {
            int rlo = mw * 64 + i * 16 + (lane >> 2);
#pragma unroll
            for (int half = 0; half < 2; ++half) {
                int rl = rlo + half * 8;
                float x2v = s_x2[rl];
                float thr = s_min[rl] + MARGIN;
                unsigned long long mk = s_minkey[rl];
#pragma unroll
                for (int j = 0; j < 4; ++j) {
                    int c0 = nw * 32 + j * 8 + (lane & 3) * 2;
#pragma unroll
                    for (int c = 0; c < 2; ++c) {
                        float d = __fadd_rn(
                            __fsub_rn(x2v, __fmul_rn(2.0f, acc[i][j][half * 2 + c])),
                            s_c2[c0 + c]);
                        if (d <= thr) {
                            unsigned long long k =
                                ((unsigned long long)__float_as_uint(d) << 32) |
                                (unsigned)(col0 + c0 + c);
                            if (k != mk) {
                                int grow = row0 + rl;
                                int pos = atomicAdd(&g_ccnt[grow], 1);
                                if (pos < CAP) g_cand[(size_t)grow * CAP + pos] = k;
                            }
                        }
                    }
                }
            }
        }
        __syncthreads();  // overlays + s_c2/s_x2 safe before next tile
    }

    // =================== barrier: all phase-1 work visible ===============
    grid_barrier(nblk);

    // overlays into dead stage-0 region for phase 2
    int* s_list = reinterpret_cast<int*>(dsm);            // 8*192*4 = 6144
    int* s_cnt = reinterpret_cast<int*>(dsm + 6144);      // 32
    double* sred = reinterpret_cast<double*>(dsm + 6176); // 2048

    // =================== phase 2: grid-stride over 1024 row-groups =======
    for (int job = blockIdx.x; job < NROWJOBS; job += nblk) {
        const int row = job * 8 + wid;

        unsigned long long k1 = g_part[(size_t)row * NTILES + lane];
        unsigned long long k2 = g_part[(size_t)row * NTILES + 32 + lane];
        unsigned long long m = k1 < k2 ? k1 : k2;
#pragma unroll
        for (int s = 16; s; s >>= 1) {
            unsigned long long o = __shfl_xor_sync(0xffffffffu, m, s);
            if (o < m) m = o;
        }
        m = __shfl_sync(0xffffffffu, m, 0);
        float thr = __uint_as_float((uint32_t)(m >> 32)) + MARGIN;

        if (lane == 0) s_cnt[wid] = 0;
        __syncwarp();
        int cnt = g_ccnt[row];
        bool ovf = cnt > CAP;
        if (!ovf) {
            if (__uint_as_float((uint32_t)(k1 >> 32)) <= thr) {
                int pos = atomicAdd(&s_cnt[wid], 1);
                s_list[wid * 192 + pos] = (int)(k1 & 0xffffffffu);
            }
            if (__uint_as_float((uint32_t)(k2 >> 32)) <= thr) {
                int pos = atomicAdd(&s_cnt[wid], 1);
                s_list[wid * 192 + pos] = (int)(k2 & 0xffffffffu);
            }
            for (int e = lane; e < cnt; e += 32) {
                unsigned long long k = g_cand[(size_t)row * CAP + e];
                if (__uint_as_float((uint32_t)(k >> 32)) <= thr) {
                    int pos = atomicAdd(&s_cnt[wid], 1);
                    s_list[wid * 192 + pos] = (int)(k & 0xffffffffu);
                }
            }
        }
        __syncwarp();
        int M = ovf ? KCODES : s_cnt[wid];

        const float* zp = ze + (size_t)row * D_DIM;
        float x2v = g_x2[row];
        unsigned long long best = ~0ull;
        for (int c = lane; c < M; c += 32) {
            int code = ovf ? c : s_list[wid * 192 + c];
            const float* cp = cb + (size_t)code * D_DIM;
            float a = 0.0f;  // exact serial fp32 chain (verified R2 values)
#pragma unroll 8
            for (int k = 0; k < D_DIM; ++k) a = fmaf(zp[k], cp[k], a);
            float d = __fadd_rn(__fsub_rn(x2v, __fmul_rn(2.0f, a)), g_c2[code]);
            unsigned long long key =
                ((unsigned long long)__float_as_uint(d) << 32) | (unsigned)code;
            if (key < best) best = key;
        }
#pragma unroll
        for (int s = 16; s; s >>= 1) {
            unsigned long long o = __shfl_xor_sync(0xffffffffu, best, s);
            if (o < best) best = o;
        }
        int idx = (int)(best & 0xffffffffu);
        if (lane == 0) out_idx[row] = (float)idx;

        // fused gather: z_q_st row + loss partial (exact verified ops)
        const float* cp = cb + (size_t)idx * D_DIM + lane * 8;
        const float* zq = zp + lane * 8;
        float* op = out_zq + (size_t)row * D_DIM + lane * 8;
        double s = 0.0;
#pragma unroll
        for (int e = 0; e < 8; ++e) {
            float z = zq[e], c = cp[e];
            op[e] = __fadd_rn(z, __fsub_rn(c, z));  // z + (z_q - z)
            float df = __fsub_rn(z, c);
            s += (double)__fmul_rn(df, df);
        }
        sred[tid] = s;
        __syncthreads();
        for (int off = 128; off; off >>= 1) {
            if (tid < off) sred[tid] += sred[tid + off];
            __syncthreads();
        }
        if (tid == 0) g_loss_part[job] = sred[0];
        __syncthreads();
    }

    // =================== barrier + final loss reduction ==================
    grid_barrier(2u * nblk);
    if (blockIdx.x == 0) {
        double s = 0.0;
        for (int i = tid; i < NROWJOBS; i += 256) s += g_loss_part[i];
        sred[tid] = s;
        __syncthreads();
        for (int off = 128; off; off >>= 1) {
            if (tid < off) sred[tid] += sred[tid + off];
            __syncthreads();
        }
        if (tid == 0) {
            float v = (float)(sred[0] / (double)(NROWS * D_DIM));
            // vq_loss = codebook_loss + 0.25 * commitment_loss
            *out_loss = __fadd_rn(v, __fmul_rn(0.25f, v));
        }
    }
}

// --------------------------------- launch --------------------------------
extern "C" void kernel_launch(void* const* d_in, const int* in_sizes, int n_in,
                              void* d_out, int out_size) {
    const float* ze = (const float*)d_in[0];
    const float* cb = (const float*)d_in[1];
    float* out = (float*)d_out;

    const int N = in_sizes[0] / D_DIM;  // 8192
    const int K = in_sizes[1] / D_DIM;  // 8192

    int smc = 0;
    cudaDeviceGetAttribute(&smc, cudaDevAttrMultiProcessorCount, 0);
    const int grid = 2 * smc;  // exactly co-resident (96KB/CTA -> 2 per SM)

    cudaFuncSetAttribute(fused_kernel,
                         cudaFuncAttributeMaxDynamicSharedMemorySize, 98304);

    split_kernel<<<(N + K) / 8, 256>>>(ze, cb, N, K);

    cudaLaunchAttribute pdl[1];
    pdl[0].id = cudaLaunchAttributeProgrammaticStreamSerialization;
    pdl[0].val.programmaticStreamSerializationAllowed = 1;

    cudaLaunchConfig_t cfg = {};
    cfg.gridDim = dim3(grid);
    cfg.blockDim = dim3(256);
    cfg.dynamicSmemBytes = 98304;
    cfg.stream = 0;
    cfg.attrs = pdl;
    cfg.numAttrs = 1;
    cudaLaunchKernelEx(&cfg, fused_kernel, ze, cb, out,
                       out + (size_t)N * D_DIM,
                       out + (size_t)N * D_DIM + N);
}